// round 14
// baseline (speedup 1.0000x reference)
#include <cuda_runtime.h>
#include <cstdint>

typedef unsigned long long ull;

#define BATCH 16
#define HH 128
#define WW 128
#define LANES 64          // 128 channels = 64 ull lanes
#define TROWS 32          // output rows per block (single-wave grid: 512 blocks)
#define TCOLS 16          // output cols per block
#define NCOLS 18          // staged cols per row segment (halo included)
#define RING 5            // ring depth (5*18*64*8 = 46080 B static smem)
#define SEG_ULL (NCOLS * LANES)          // 1152 ull per row segment
#define SEG_BYTES (SEG_ULL * 8)          // 9216
#define SEG_CHUNKS (SEG_BYTES / 16)      // 576 x 16B
#define THREADS 256

// ---- packed fp32x2 primitives (sm_103a) ----
__device__ __forceinline__ ull mulp(ull a, ull b) {
    ull r; asm("mul.rn.f32x2 %0, %1, %2;" : "=l"(r) : "l"(a), "l"(b)); return r;
}
__device__ __forceinline__ ull addp(ull a, ull b) {
    ull r; asm("add.rn.f32x2 %0, %1, %2;" : "=l"(r) : "l"(a), "l"(b)); return r;
}
__device__ __forceinline__ ull fmap(ull a, ull b, ull c) {
    ull r; asm("fma.rn.f32x2 %0, %1, %2, %3;" : "=l"(r) : "l"(a), "l"(b), "l"(c)); return r;
}
__device__ __forceinline__ ull pack2f(float x) {
    ull r; asm("mov.b64 %0, {%1, %1};" : "=l"(r) : "f"(x)); return r;
}
__device__ __forceinline__ ull absp(ull u) { return u & 0x7FFFFFFF7FFFFFFFULL; }
__device__ __forceinline__ ull mixp(ull x, ull y, ull w25, ull w75) {
    return fmap(x, w25, mulp(y, w75));       // 0.25x + 0.75y
}
__device__ __forceinline__ void stcs8(ull* p, ull v) {
    asm volatile("st.global.cs.b64 [%0], %1;" :: "l"(p), "l"(v) : "memory");
}

// ---- cp.async helpers ----
__device__ __forceinline__ void cp16(uint32_t saddr, const void* g) {
    // .cg: bypass L1 — staged rows are consumed from smem, never re-read via L1
    asm volatile("cp.async.cg.shared.global [%0], [%1], 16;" :: "r"(saddr), "l"(g));
}
__device__ __forceinline__ void cp_commit() {
    asm volatile("cp.async.commit_group;" ::: "memory");
}
template <int N> __device__ __forceinline__ void cp_wait() {
    asm volatile("cp.async.wait_group %0;" :: "n"(N) : "memory");
}
__device__ __forceinline__ ull lds8(uint32_t a) {
    ull v; asm volatile("ld.shared.b64 %0, [%1];" : "=l"(v) : "r"(a)); return v;
}

// block = 256 threads: lane = tid&63 (ull channel), cg = tid>>6 (4 col groups of 4)
// tile: 32 output rows x 16 output cols x 128 ch; grid = (8, 4, 16) = 512 blocks
// minBlocksPerMultiprocessor=4 caps regs at 64 -> 4 resident blocks/SM -> ONE wave
__global__ __launch_bounds__(THREADS, 4)
void act_filter_kernel(const ull* __restrict__ X, ull* __restrict__ O) {
    __shared__ ull ring[RING][SEG_ULL];

    const int tid  = threadIdx.x;
    const int lane = tid & (LANES - 1);
    const int cg   = tid >> 6;                  // 0..3
    const int j0   = blockIdx.x * TCOLS;
    const int i0   = blockIdx.y * TROWS;
    const int b    = blockIdx.z;

    // staged column range start (so [cstart, cstart+17] subset of [0,127])
    const int cstart = (j0 == 0) ? 0 : ((j0 == WW - TCOLS) ? (WW - NCOLS) : j0 - 1);

    const ull w25 = pack2f(0.25f);
    const ull w75 = pack2f(0.75f);
    const ull ca  = pack2f(0.12625f);   // 0.505*0.25  (lrelu = 0.505u + 0.495|u|)
    const ull cb  = pack2f(0.12375f);   // 0.495*0.25

    const uint32_t sring = (uint32_t)__cvta_generic_to_shared(&ring[0][0]);

    // producer: stage input row k (k indexes rows i0-1 .. i0+TROWS) into slot k%RING
    auto issue_row = [&](int k) {
        int rin = i0 - 1 + k;
        rin = (rin < 0) ? 0 : ((rin > HH - 1) ? HH - 1 : rin);
        const char* gsrc = (const char*)(X + ((size_t)((b * HH + rin) * WW + cstart)) * LANES);
        const uint32_t sbase = sring + (k % RING) * SEG_BYTES;
#pragma unroll
        for (int c = tid; c < SEG_CHUNKS; c += THREADS)
            cp16(sbase + c * 16, gsrc + (size_t)c * 16);
        cp_commit();
    };

    // prologue: stage rows k = 0..3
    issue_row(0); issue_row(1); issue_row(2); issue_row(3);

    // this thread's 6 clamped source-column byte offsets within a segment
    const int j0c = j0 + cg * 4;
    uint32_t wcb[6];
#pragma unroll
    for (int t = 0; t < 6; t++) {
        int c = j0c - 1 + t;
        c = (c < 0) ? 0 : ((c > WW - 1) ? WW - 1 : c);
        wcb[t] = (uint32_t)(((c - cstart) * LANES + lane) * 8);
    }

    ull* __restrict__ po = O + ((size_t)((b * HH + i0) * WW + j0c)) * LANES + lane;

    // rotating raw-x window: xw[k%3][t] = input row k, source col t
    ull xw[3][6];

    // prime window with rows k=0 (i0-1) and k=1 (i0)
    cp_wait<2>();
    __syncthreads();
#pragma unroll
    for (int k = 0; k < 2; k++) {
        const uint32_t sbase = sring + k * SEG_BYTES;
#pragma unroll
        for (int t = 0; t < 6; t++) xw[k][t] = lds8(sbase + wcb[t]);
    }

#pragma unroll
    for (int r = 0; r < TROWS; r++) {
        // row k=r+2 must be resident; groups issued so far: 4 + r
        if (r < TROWS - 1) cp_wait<1>(); else cp_wait<0>();
        __syncthreads();                            // publish staged rows; retire slot k=r-1
        if (r + 4 <= TROWS + 1) issue_row(r + 4);   // stage ahead into freed slot

        // load ONLY the new input row (k=r+2) into the rotating window
        {
            const uint32_t sbase = sring + ((r + 2) % RING) * SEG_BYTES;
#pragma unroll
            for (int t = 0; t < 6; t++) xw[(r + 2) % 3][t] = lds8(sbase + wcb[t]);
        }

        const ull* xm = xw[r % 3];         // input row i-1
        const ull* x0 = xw[(r + 1) % 3];   // input row i
        const ull* xp = xw[(r + 2) % 3];   // input row i+1

        // vertical mixes for the two up-rows
        ull vp[6], vq[6];
#pragma unroll
        for (int t = 0; t < 6; t++) {
            vp[t] = mixp(xm[t], x0[t], w25, w75);
            vq[t] = mixp(xp[t], x0[t], w25, w75);
        }

        // horizontal mixes + blend for 4 output cols
#pragma unroll
        for (int jj = 0; jj < 4; jj++) {
            const int t = jj + 1;
            ull u00 = mixp(vp[t - 1], vp[t], w25, w75);
            ull u01 = mixp(vp[t + 1], vp[t], w25, w75);
            ull u10 = mixp(vq[t - 1], vq[t], w25, w75);
            ull u11 = mixp(vq[t + 1], vq[t], w25, w75);
            ull sl = addp(addp(u00, u01), addp(u10, u11));
            ull sa = addp(addp(absp(u00), absp(u01)), addp(absp(u10), absp(u11)));
            stcs8(po + (size_t)r * WW * LANES + jj * LANES,
                  fmap(sl, ca, mulp(sa, cb)));
        }
    }
}

extern "C" void kernel_launch(void* const* d_in, const int* in_sizes, int n_in,
                              void* d_out, int out_size) {
    const ull* X = (const ull*)d_in[0];
    ull* O = (ull*)d_out;
    dim3 block(THREADS, 1, 1);
    dim3 grid(WW / TCOLS, HH / TROWS, BATCH);   // 8, 4, 16 = 512 blocks
    act_filter_kernel<<<grid, block>>>(X, O);
}

// round 15
// speedup vs baseline: 1.0423x; 1.0423x over previous
#include <cuda_runtime.h>
#include <cstdint>

typedef unsigned long long ull;

#define BATCH 16
#define HH 128
#define WW 128
#define LANES 64          // 128 channels = 64 ull lanes
#define TROWS 16          // output rows per block
#define TCOLS 16          // output cols per block
#define NCOLS 18          // staged cols per row segment (halo included)
#define RING 5            // ring depth (5*18*64*8 = 46080 B static smem)
#define SEG_ULL (NCOLS * LANES)          // 1152 ull per row segment
#define SEG_BYTES (SEG_ULL * 8)          // 9216
#define SEG_CHUNKS (SEG_BYTES / 16)      // 576 x 16B
#define THREADS 256

// ---- packed fp32x2 primitives (sm_103a) ----
__device__ __forceinline__ ull mulp(ull a, ull b) {
    ull r; asm("mul.rn.f32x2 %0, %1, %2;" : "=l"(r) : "l"(a), "l"(b)); return r;
}
__device__ __forceinline__ ull addp(ull a, ull b) {
    ull r; asm("add.rn.f32x2 %0, %1, %2;" : "=l"(r) : "l"(a), "l"(b)); return r;
}
__device__ __forceinline__ ull fmap(ull a, ull b, ull c) {
    ull r; asm("fma.rn.f32x2 %0, %1, %2, %3;" : "=l"(r) : "l"(a), "l"(b), "l"(c)); return r;
}
__device__ __forceinline__ ull pack2f(float x) {
    ull r; asm("mov.b64 %0, {%1, %1};" : "=l"(r) : "f"(x)); return r;
}
__device__ __forceinline__ ull absp(ull u) { return u & 0x7FFFFFFF7FFFFFFFULL; }
__device__ __forceinline__ void stcs8(ull* p, ull v) {
    asm volatile("st.global.cs.b64 [%0], %1;" :: "l"(p), "l"(v) : "memory");
}

// ---- cp.async helpers ----
__device__ __forceinline__ void cp16(uint32_t saddr, const void* g) {
    asm volatile("cp.async.ca.shared.global [%0], [%1], 16;" :: "r"(saddr), "l"(g));
}
__device__ __forceinline__ void cp_commit() {
    asm volatile("cp.async.commit_group;" ::: "memory");
}
template <int N> __device__ __forceinline__ void cp_wait() {
    asm volatile("cp.async.wait_group %0;" :: "n"(N) : "memory");
}
__device__ __forceinline__ ull lds8(uint32_t a) {
    ull v; asm volatile("ld.shared.b64 %0, [%1];" : "=l"(v) : "r"(a)); return v;
}

// block = 256 threads: lane = tid&63 (ull channel), cg = tid>>6 (4 col groups of 4)
// tile: 16 output rows x 16 output cols x 128 ch; grid = (8, 8, 16) = 1024 blocks
// minBlocksPerMultiprocessor=4 caps regs at 64 -> 4 resident blocks/SM
__global__ __launch_bounds__(THREADS, 4)
void act_filter_kernel(const ull* __restrict__ X, ull* __restrict__ O) {
    __shared__ ull ring[RING][SEG_ULL];

    const int tid  = threadIdx.x;
    const int lane = tid & (LANES - 1);
    const int cg   = tid >> 6;                  // 0..3
    const int j0   = blockIdx.x * TCOLS;
    const int i0   = blockIdx.y * TROWS;
    const int b    = blockIdx.z;

    // staged column range start (so [cstart, cstart+17] subset of [0,127])
    const int cstart = (j0 == 0) ? 0 : ((j0 == WW - TCOLS) ? (WW - NCOLS) : j0 - 1);

    const ull w25 = pack2f(0.25f);
    const ull w75 = pack2f(0.75f);
    const ull ca  = pack2f(0.12625f);   // 0.505*0.25  (lrelu = 0.505u + 0.495|u|)
    const ull cb  = pack2f(0.12375f);   // 0.495*0.25

    const uint32_t sring = (uint32_t)__cvta_generic_to_shared(&ring[0][0]);

    // producer: stage input row k (k indexes rows i0-1 .. i0+16) into slot k%RING
    auto issue_row = [&](int k) {
        int rin = i0 - 1 + k;
        rin = (rin < 0) ? 0 : ((rin > HH - 1) ? HH - 1 : rin);
        const char* gsrc = (const char*)(X + ((size_t)((b * HH + rin) * WW + cstart)) * LANES);
        const uint32_t sbase = sring + (k % RING) * SEG_BYTES;
#pragma unroll
        for (int c = tid; c < SEG_CHUNKS; c += THREADS)
            cp16(sbase + c * 16, gsrc + (size_t)c * 16);
        cp_commit();
    };

    // prologue: stage rows k = 0..3
    issue_row(0); issue_row(1); issue_row(2); issue_row(3);

    // this thread's 6 clamped source-column byte offsets within a segment
    const int j0c = j0 + cg * 4;
    uint32_t wcb[6];
#pragma unroll
    for (int t = 0; t < 6; t++) {
        int c = j0c - 1 + t;
        c = (c < 0) ? 0 : ((c > WW - 1) ? WW - 1 : c);
        wcb[t] = (uint32_t)(((c - cstart) * LANES + lane) * 8);
    }

    ull* __restrict__ po = O + ((size_t)((b * HH + i0) * WW + j0c)) * LANES + lane;

    // rotating raw-x window: xw[k%3][t] = input row k, source col t
    ull xw[3][6];

    // prime window with rows k=0 (i0-1) and k=1 (i0); rows 0..2 complete (4 issued)
    cp_wait<2>();
    __syncthreads();
#pragma unroll
    for (int k = 0; k < 2; k++) {
        const uint32_t sbase = sring + k * SEG_BYTES;
#pragma unroll
        for (int t = 0; t < 6; t++) xw[k][t] = lds8(sbase + wcb[t]);
    }

#pragma unroll
    for (int r = 0; r < TROWS; r++) {
        // issue row r+4 FIRST (slot holds row r-1, last read 2 syncs ago -> safe),
        // so the copy engine works during our wait+barrier.
        if (r + 4 <= TROWS + 1) issue_row(r + 4);

        // need rows <= r+2 complete; outstanding allowed = {r+3, r+4}
        if (r + 4 <= TROWS + 1)      cp_wait<2>();
        else if (r + 3 <= TROWS + 1) cp_wait<1>();
        else                         cp_wait<0>();
        __syncthreads();                     // publish staged rows block-wide

        // load ONLY the new input row (k=r+2) into the rotating window
        {
            const uint32_t sbase = sring + ((r + 2) % RING) * SEG_BYTES;
#pragma unroll
            for (int t = 0; t < 6; t++) xw[(r + 2) % 3][t] = lds8(sbase + wcb[t]);
        }

        const ull* xm = xw[r % 3];         // input row i-1
        const ull* x0 = xw[(r + 1) % 3];   // input row i
        const ull* xp = xw[(r + 2) % 3];   // input row i+1

        // vertical mixes for the two up-rows (shared 0.75*x0 term)
        ull vp[6], vq[6];
#pragma unroll
        for (int t = 0; t < 6; t++) {
            ull t75 = mulp(x0[t], w75);
            vp[t] = fmap(xm[t], w25, t75);   // 0.25 x[i-1] + 0.75 x[i]
            vq[t] = fmap(xp[t], w25, t75);   // 0.25 x[i+1] + 0.75 x[i]
        }

        // horizontal mixes + blend for 4 output cols (shared 0.75*v[t] terms)
#pragma unroll
        for (int jj = 0; jj < 4; jj++) {
            const int t = jj + 1;
            ull hp = mulp(vp[t], w75);
            ull hq = mulp(vq[t], w75);
            ull u00 = fmap(vp[t - 1], w25, hp);
            ull u01 = fmap(vp[t + 1], w25, hp);
            ull u10 = fmap(vq[t - 1], w25, hq);
            ull u11 = fmap(vq[t + 1], w25, hq);
            ull sl = addp(addp(u00, u01), addp(u10, u11));
            ull sa = addp(addp(absp(u00), absp(u01)), addp(absp(u10), absp(u11)));
            stcs8(po + (size_t)r * WW * LANES + jj * LANES,
                  fmap(sl, ca, mulp(sa, cb)));
        }
    }
}

extern "C" void kernel_launch(void* const* d_in, const int* in_sizes, int n_in,
                              void* d_out, int out_size) {
    const ull* X = (const ull*)d_in[0];
    ull* O = (ull*)d_out;
    dim3 block(THREADS, 1, 1);
    dim3 grid(WW / TCOLS, HH / TROWS, BATCH);   // 8, 8, 16
    act_filter_kernel<<<grid, block>>>(X, O);
}